// round 3
// baseline (speedup 1.0000x reference)
#include <cuda_runtime.h>
#include <math.h>

// ============================================================================
// RieBatchNet (SPDNet forward): BiMap -> SPD-BatchNorm -> ReEig (x2),
// BiMap -> SPD-BatchNorm -> LogEig -> Linear head.
// Batched symmetric eig via parallel cyclic Jacobi, one CTA per matrix.
// ============================================================================

#define NT 256
#define NSAMP 8192
#define EPS_RE 1e-4f
#define NGRP 64           // reduction groups (64 x 128 = 8192)
#define SPG  (NSAMP/NGRP) // samples per group = 128

// ------------------ device scratch (static, no allocation) ------------------
__device__ float g_bufA[(size_t)NSAMP * 58 * 58];
__device__ float g_bufB[(size_t)NSAMP * 58 * 58];
__device__ float g_part[NGRP * 58 * 58];
__device__ float g_accM[58 * 58];
__device__ float g_accL[58 * 58];
__device__ float g_M0s[58 * 58];
__device__ float g_M0is[58 * 58];
__device__ float g_G[58 * 58];
__device__ float g_P[58 * 58];
__device__ float g_Ws1[58 * 58];
__device__ float g_Ws2[54 * 54];
__device__ float g_Ws3[50 * 50];

// ---------------------------------------------------------------------------
__device__ __forceinline__ float warp_sum(float v) {
#pragma unroll
    for (int o = 16; o > 0; o >>= 1) v += __shfl_xor_sync(0xffffffffu, v, o);
    return v;
}

// deterministic block reduction; all threads get the result
__device__ __forceinline__ float block_sum(float v, float* sred, int tid) {
    v = warp_sum(v);
    if ((tid & 31) == 0) sred[tid >> 5] = v;
    __syncthreads();
    if (tid == 0) {
        float t = 0.f;
#pragma unroll
        for (int w = 0; w < NT / 32; w++) t += sred[w];
        sred[8] = t;
    }
    __syncthreads();
    return sred[8];
}

// ---------------------------------------------------------------------------
// Parallel cyclic Jacobi on shared A (DxD row-major). V accumulates
// eigenvectors: on exit A0 = V diag(A_ii) V^T. D must be even.
// Deterministic early exit on off-diagonal Frobenius norm.
// Rotation loops are indexed so consecutive threads touch consecutive rows
// of the same pair (stride-D shared access -> <=2-way bank conflict).
// ---------------------------------------------------------------------------
template <int D>
__device__ void jacobi(float* A, float* V, float* sc, float* ss_,
                       int* sp, int* sq, float* sred, int tid) {
    const int m = D / 2, M = D - 1;
    // V = I
    for (int e = tid; e < D * D; e += NT) V[e] = ((e / D) == (e % D)) ? 1.f : 0.f;
    // Frobenius norm of input
    float fs = 0.f;
    for (int e = tid; e < D * D; e += NT) { float v = A[e]; fs += v * v; }
    float fro2 = block_sum(fs, sred, tid);   // also syncs V init
    float skipT = 1e-10f * sqrtf(fro2);
    float tol2 = 1e-13f * fro2;

    for (int sw = 0; sw < 16; ++sw) {
        for (int r = 0; r < M; ++r) {
            if (tid < m) {
                int a, b;
                if (tid == 0) { a = M; b = r; }
                else { a = (r + tid) % M; b = (r - tid + M) % M; }
                int p = a < b ? a : b;
                int q = a < b ? b : a;
                sp[tid] = p; sq[tid] = q;
                float apq = A[p * D + q];
                float c = 1.f, s = 0.f;
                if (fabsf(apq) > skipT) {
                    float tau = (A[q * D + q] - A[p * D + p]) / (2.f * apq);
                    float t = 1.f / (fabsf(tau) + sqrtf(1.f + tau * tau));
                    t = (tau >= 0.f) ? t : -t;
                    c = 1.f / sqrtf(1.f + t * t);
                    s = t * c;
                }
                sc[tid] = c; ss_[tid] = s;
            }
            __syncthreads();
            // column rotations: A <- A*J, V <- V*J (disjoint column pairs)
            for (int e = tid; e < D * m; e += NT) {
                int k = e / D;          // pair index (same for 58..64 consecutive lanes)
                int i = e - k * D;      // row: consecutive lanes -> consecutive rows
                float s = ss_[k];
                if (s != 0.f) {
                    float c = sc[k];
                    int p = sp[k], q = sq[k];
                    float x = A[i * D + p], y = A[i * D + q];
                    A[i * D + p] = c * x - s * y;
                    A[i * D + q] = s * x + c * y;
                    x = V[i * D + p]; y = V[i * D + q];
                    V[i * D + p] = c * x - s * y;
                    V[i * D + q] = s * x + c * y;
                }
            }
            __syncthreads();
            // row rotations: A <- J^T * A (disjoint row pairs)
            for (int e = tid; e < D * m; e += NT) {
                int k = e / D;
                int j = e - k * D;      // column: consecutive lanes -> consecutive cols
                float s = ss_[k];
                if (s != 0.f) {
                    float c = sc[k];
                    int p = sp[k], q = sq[k];
                    float x = A[p * D + j], y = A[q * D + j];
                    A[p * D + j] = c * x - s * y;
                    A[q * D + j] = s * x + c * y;
                }
            }
            __syncthreads();
        }
        float off = 0.f;
        for (int e = tid; e < D * D; e += NT) {
            int i = e / D, j = e - i * D;
            if (i != j) { float v = A[e]; off += v * v; }
        }
        if (block_sum(off, sred, tid) <= tol2) break;
    }
    __syncthreads();
}

template <int D>
__device__ void symmetrize_sh(float* A, int tid) {
    float tmp[(D * D + NT - 1) / NT];
    int c = 0;
    for (int e = tid; e < D * D; e += NT) {
        int i = e / D, j = e - i * D;
        tmp[c++] = 0.5f * (A[e] + A[j * D + i]);
    }
    __syncthreads();
    c = 0;
    for (int e = tid; e < D * D; e += NT) A[e] = tmp[c++];
    __syncthreads();
}

// ---------------------------------------------------------------------------
// BiMap: Y_n = W X_n W^T   (W: Dout x Din)
// ---------------------------------------------------------------------------
template <int Din, int Dout>
__global__ void __launch_bounds__(NT)
bimap_kernel(const float* __restrict__ X,
             const float* __restrict__ W,
             float* __restrict__ Y) {
    __shared__ float sX[Din * Din];
    __shared__ float sW[Dout * Din];
    __shared__ float sT[Dout * Din];
    int tid = threadIdx.x;
    size_t n = blockIdx.x;
    const float* Xn = X + n * Din * Din;
    for (int e = tid; e < Din * Din; e += NT) sX[e] = Xn[e];
    for (int e = tid; e < Dout * Din; e += NT) sW[e] = W[e];
    __syncthreads();
    for (int e = tid; e < Dout * Din; e += NT) {
        int i = e / Din, j = e - i * Din;
        float acc = 0.f;
#pragma unroll 4
        for (int k = 0; k < Din; k++) acc += sW[i * Din + k] * sX[k * Din + j];
        sT[e] = acc;
    }
    __syncthreads();
    float* Yn = Y + n * Dout * Dout;
    for (int e = tid; e < Dout * Dout; e += NT) {
        int i = e / Dout, j = e - i * Dout;
        float acc = 0.f;
#pragma unroll 4
        for (int k = 0; k < Din; k++) acc += sT[i * Din + k] * sW[j * Din + k];
        Yn[e] = acc;
    }
}

// ---------------------------------------------------------------------------
// Batch-mean reduction (deterministic two stage). red2 scales by 1/NSAMP and
// symmetrizes.
// ---------------------------------------------------------------------------
template <int D>
__global__ void __launch_bounds__(NT)
red1_kernel(const float* __restrict__ src, float* __restrict__ part) {
    int e = blockIdx.x * NT + threadIdx.x;
    int g = blockIdx.y;
    if (e >= D * D) return;
    float s = 0.f;
    const float* p = src + (size_t)g * SPG * D * D + e;
    for (int i = 0; i < SPG; i++) s += p[(size_t)i * D * D];
    part[g * D * D + e] = s;
}

template <int D>
__global__ void __launch_bounds__(NT)
red2_kernel(const float* __restrict__ part, float* __restrict__ dst) {
    __shared__ float Msh[D * D];
    int tid = threadIdx.x;
    for (int e = tid; e < D * D; e += NT) {
        float s = 0.f;
        for (int g = 0; g < NGRP; g++) s += part[g * D * D + e];
        Msh[e] = s * (1.f / (float)NSAMP);
    }
    __syncthreads();
    for (int e = tid; e < D * D; e += NT) {
        int i = e / D, j = e - i * D;
        dst[e] = 0.5f * (Msh[e] + Msh[j * D + i]);
    }
}

// ---------------------------------------------------------------------------
// Small single-matrix eig kernels (1 block each)
// ---------------------------------------------------------------------------
#define EIG_DECL(D)                                      \
    __shared__ float U0[D * D]; __shared__ float U2[D * D]; \
    __shared__ float sc[D / 2]; __shared__ float ssn[D / 2]; \
    __shared__ int sp[D / 2]; __shared__ int sq[D / 2];     \
    __shared__ float sred[9]; __shared__ float sf[D];       \
    int tid = threadIdx.x;

// Ws = sqrtm(Gw)
template <int D>
__global__ void __launch_bounds__(NT)
ws_kernel(const float* __restrict__ Gw, float* __restrict__ Ws) {
    EIG_DECL(D)
    for (int e = tid; e < D * D; e += NT) U0[e] = Gw[e];
    __syncthreads();
    symmetrize_sh<D>(U0, tid);
    jacobi<D>(U0, U2, sc, ssn, sp, sq, sred, tid);
    for (int k = tid; k < D; k += NT) sf[k] = sqrtf(fmaxf(U0[k * D + k], 0.f));
    __syncthreads();
    for (int e = tid; e < D * D; e += NT) {
        int i = e / D, j = e - i * D;
        float acc = 0.f;
#pragma unroll 4
        for (int k = 0; k < D; k++) acc += U2[i * D + k] * sf[k] * U2[j * D + k];
        Ws[e] = acc;
    }
}

// M0s = sqrtm(M0), M0is = isqrtm(M0)
template <int D>
__global__ void __launch_bounds__(NT)
eig_m0_kernel(const float* __restrict__ M0,
              float* __restrict__ M0s, float* __restrict__ M0is) {
    EIG_DECL(D)
    for (int e = tid; e < D * D; e += NT) U0[e] = M0[e];
    __syncthreads();
    jacobi<D>(U0, U2, sc, ssn, sp, sq, sred, tid);
    for (int k = tid; k < D; k += NT) sf[k] = sqrtf(fmaxf(U0[k * D + k], 1e-30f));
    __syncthreads();
    for (int e = tid; e < D * D; e += NT) {
        int i = e / D, j = e - i * D;
        float acc = 0.f;
#pragma unroll 4
        for (int k = 0; k < D; k++) acc += U2[i * D + k] * sf[k] * U2[j * D + k];
        M0s[e] = acc;
    }
    __syncthreads();
    for (int k = tid; k < D; k += NT) sf[k] = 1.f / sf[k];
    __syncthreads();
    for (int e = tid; e < D * D; e += NT) {
        int i = e / D, j = e - i * D;
        float acc = 0.f;
#pragma unroll 4
        for (int k = 0; k < D; k++) acc += U2[i * D + k] * sf[k] * U2[j * D + k];
        M0is[e] = acc;
    }
}

// G = sym(M0s expm(L) M0s)
template <int D>
__global__ void __launch_bounds__(NT)
formG_kernel(const float* __restrict__ L,
             const float* __restrict__ M0s, float* __restrict__ G) {
    EIG_DECL(D)
    __shared__ float U1[D * D];
    for (int e = tid; e < D * D; e += NT) U0[e] = L[e];
    for (int e = tid; e < D * D; e += NT) U1[e] = M0s[e];
    __syncthreads();
    jacobi<D>(U0, U2, sc, ssn, sp, sq, sred, tid);
    for (int k = tid; k < D; k += NT) sf[k] = expf(U0[k * D + k]);
    __syncthreads();
    // E = V exp V^T -> U0  (reads U2, writes U0)
    {
        float tmp[(D * D + NT - 1) / NT];
        int c = 0;
        for (int e = tid; e < D * D; e += NT) {
            int i = e / D, j = e - i * D;
            float acc = 0.f;
#pragma unroll 4
            for (int k = 0; k < D; k++) acc += U2[i * D + k] * sf[k] * U2[j * D + k];
            tmp[c++] = acc;
        }
        __syncthreads();
        c = 0;
        for (int e = tid; e < D * D; e += NT) U0[e] = tmp[c++];
        __syncthreads();
    }
    // T = M0s @ E -> U2 (V dead)
    for (int e = tid; e < D * D; e += NT) {
        int i = e / D, j = e - i * D;
        float acc = 0.f;
#pragma unroll 4
        for (int k = 0; k < D; k++) acc += U1[i * D + k] * U0[k * D + j];
        U2[e] = acc;
    }
    __syncthreads();
    // G = T @ M0s -> registers -> sym -> global
    {
        float tmp[(D * D + NT - 1) / NT];
        int c = 0;
        for (int e = tid; e < D * D; e += NT) {
            int i = e / D, j = e - i * D;
            float acc = 0.f;
#pragma unroll 4
            for (int k = 0; k < D; k++) acc += U2[i * D + k] * U1[k * D + j];
            tmp[c++] = acc;
        }
        __syncthreads();
        c = 0;
        for (int e = tid; e < D * D; e += NT) U0[e] = tmp[c++];
        __syncthreads();
        c = 0;
        for (int e = tid; e < D * D; e += NT) {
            int i = e / D, j = e - i * D;
            tmp[c++] = 0.5f * (U0[e] + U0[j * D + i]);
        }
        __syncthreads();
        c = 0;
        for (int e = tid; e < D * D; e += NT) G[e] = tmp[c++];
    }
}

// P = Ws @ isqrtm(G)
template <int D>
__global__ void __launch_bounds__(NT)
eig_p_kernel(const float* __restrict__ G,
             const float* __restrict__ Ws, float* __restrict__ P) {
    EIG_DECL(D)
    __shared__ float U1[D * D];
    for (int e = tid; e < D * D; e += NT) U0[e] = G[e];
    for (int e = tid; e < D * D; e += NT) U1[e] = Ws[e];
    __syncthreads();
    jacobi<D>(U0, U2, sc, ssn, sp, sq, sred, tid);
    for (int k = tid; k < D; k += NT)
        sf[k] = 1.f / sqrtf(fmaxf(U0[k * D + k], 1e-30f));
    __syncthreads();
    // Gis = V f V^T -> U0 (reads U2)
    {
        float tmp[(D * D + NT - 1) / NT];
        int c = 0;
        for (int e = tid; e < D * D; e += NT) {
            int i = e / D, j = e - i * D;
            float acc = 0.f;
#pragma unroll 4
            for (int k = 0; k < D; k++) acc += U2[i * D + k] * sf[k] * U2[j * D + k];
            tmp[c++] = acc;
        }
        __syncthreads();
        c = 0;
        for (int e = tid; e < D * D; e += NT) U0[e] = tmp[c++];
        __syncthreads();
    }
    // P = Ws @ Gis -> global
    for (int e = tid; e < D * D; e += NT) {
        int i = e / D, j = e - i * D;
        float acc = 0.f;
#pragma unroll 4
        for (int k = 0; k < D; k++) acc += U1[i * D + k] * U0[k * D + j];
        P[e] = acc;
    }
}

// ---------------------------------------------------------------------------
// Per-sample: Z_n = logm(M0is X_n M0is)   (Karcher-step log)
// ---------------------------------------------------------------------------
template <int D>
__global__ void __launch_bounds__(NT)
bn_logm_kernel(const float* __restrict__ X,
               const float* __restrict__ M0is,
               float* __restrict__ Z) {
    EIG_DECL(D)
    __shared__ float U1[D * D];
    size_t n = blockIdx.x;
    const float* Xn = X + n * D * D;
    for (int e = tid; e < D * D; e += NT) U0[e] = Xn[e];
    for (int e = tid; e < D * D; e += NT) U1[e] = M0is[e];
    __syncthreads();
    // T = M0is @ X -> U2
    for (int e = tid; e < D * D; e += NT) {
        int i = e / D, j = e - i * D;
        float acc = 0.f;
#pragma unroll 4
        for (int k = 0; k < D; k++) acc += U1[i * D + k] * U0[k * D + j];
        U2[e] = acc;
    }
    __syncthreads();
    // A = T @ M0is -> U0 (X dead)
    for (int e = tid; e < D * D; e += NT) {
        int i = e / D, j = e - i * D;
        float acc = 0.f;
#pragma unroll 4
        for (int k = 0; k < D; k++) acc += U2[i * D + k] * U1[k * D + j];
        U0[e] = acc;
    }
    __syncthreads();
    symmetrize_sh<D>(U0, tid);
    jacobi<D>(U0, U2, sc, ssn, sp, sq, sred, tid);
    for (int k = tid; k < D; k += NT)
        sf[k] = logf(fmaxf(U0[k * D + k], 1e-30f));
    __syncthreads();
    float* Zn = Z + n * D * D;
    for (int e = tid; e < D * D; e += NT) {
        int i = e / D, j = e - i * D;
        float acc = 0.f;
#pragma unroll 4
        for (int k = 0; k < D; k++) acc += U2[i * D + k] * sf[k] * U2[j * D + k];
        Zn[e] = acc;
    }
}

// ---------------------------------------------------------------------------
// Per-sample: X_n <- ReEig(P X_n P^T)   (in-place; P = Ws @ Gis)
// ---------------------------------------------------------------------------
template <int D>
__global__ void __launch_bounds__(NT)
apply_reeig_kernel(float* __restrict__ X, const float* __restrict__ P) {
    EIG_DECL(D)
    __shared__ float U1[D * D];
    size_t n = blockIdx.x;
    float* Xn = X + n * D * D;
    for (int e = tid; e < D * D; e += NT) U0[e] = Xn[e];
    for (int e = tid; e < D * D; e += NT) U1[e] = P[e];
    __syncthreads();
    // T = P @ X -> U2
    for (int e = tid; e < D * D; e += NT) {
        int i = e / D, j = e - i * D;
        float acc = 0.f;
#pragma unroll 4
        for (int k = 0; k < D; k++) acc += U1[i * D + k] * U0[k * D + j];
        U2[e] = acc;
    }
    __syncthreads();
    // A = T @ P^T -> U0
    for (int e = tid; e < D * D; e += NT) {
        int i = e / D, j = e - i * D;
        float acc = 0.f;
#pragma unroll 4
        for (int k = 0; k < D; k++) acc += U2[i * D + k] * U1[j * D + k];
        U0[e] = acc;
    }
    __syncthreads();
    symmetrize_sh<D>(U0, tid);
    jacobi<D>(U0, U2, sc, ssn, sp, sq, sred, tid);
    for (int k = tid; k < D; k += NT)
        sf[k] = fmaxf(U0[k * D + k], EPS_RE);
    __syncthreads();
    for (int e = tid; e < D * D; e += NT) {
        int i = e / D, j = e - i * D;
        float acc = 0.f;
#pragma unroll 4
        for (int k = 0; k < D; k++) acc += U2[i * D + k] * sf[k] * U2[j * D + k];
        Xn[e] = acc;
    }
}

// ---------------------------------------------------------------------------
// Final: feat_n = P X_n P^T (written out), v = vec(logm(feat_n)),
//        y_n = v @ Wl^T + bl
// ---------------------------------------------------------------------------
template <int D>
__global__ void __launch_bounds__(NT)
final_kernel(const float* __restrict__ X, const float* __restrict__ P,
             const float* __restrict__ Wl, const float* __restrict__ bl,
             float* __restrict__ outY, float* __restrict__ outF) {
    EIG_DECL(D)
    __shared__ float U1[D * D];
    size_t n = blockIdx.x;
    const float* Xn = X + n * D * D;
    for (int e = tid; e < D * D; e += NT) U0[e] = Xn[e];
    for (int e = tid; e < D * D; e += NT) U1[e] = P[e];
    __syncthreads();
    // T = P @ X -> U2
    for (int e = tid; e < D * D; e += NT) {
        int i = e / D, j = e - i * D;
        float acc = 0.f;
#pragma unroll 4
        for (int k = 0; k < D; k++) acc += U1[i * D + k] * U0[k * D + j];
        U2[e] = acc;
    }
    __syncthreads();
    // feat = T @ P^T -> U0
    for (int e = tid; e < D * D; e += NT) {
        int i = e / D, j = e - i * D;
        float acc = 0.f;
#pragma unroll 4
        for (int k = 0; k < D; k++) acc += U2[i * D + k] * U1[j * D + k];
        U0[e] = acc;
    }
    __syncthreads();
    symmetrize_sh<D>(U0, tid);
    // write feat before Jacobi destroys it (jacobi does not write U0 before
    // its first internal block_sum barrier, so these reads are safe)
    float* Fn = outF + n * D * D;
    for (int e = tid; e < D * D; e += NT) Fn[e] = U0[e];
    jacobi<D>(U0, U2, sc, ssn, sp, sq, sred, tid);
    for (int k = tid; k < D; k += NT)
        sf[k] = logf(fmaxf(U0[k * D + k], 1e-30f));
    __syncthreads();
    // Z = V f V^T entries fused with y = Z . Wl^T
    float y0 = 0.f, y1 = 0.f;
    for (int e = tid; e < D * D; e += NT) {
        int i = e / D, j = e - i * D;
        float acc = 0.f;
#pragma unroll 4
        for (int k = 0; k < D; k++) acc += U2[i * D + k] * sf[k] * U2[j * D + k];
        y0 += acc * Wl[e];
        y1 += acc * Wl[D * D + e];
    }
    y0 = block_sum(y0, sred, tid);
    y1 = block_sum(y1, sred, tid);
    if (tid == 0) {
        outY[n * 2 + 0] = y0 + bl[0];
        outY[n * 2 + 1] = y1 + bl[1];
    }
}

// ---------------------------------------------------------------------------
extern "C" void kernel_launch(void* const* d_in, const int* in_sizes, int n_in,
                              void* d_out, int out_size) {
    (void)in_sizes; (void)n_in; (void)out_size;
    const float* x  = (const float*)d_in[0];
    const float* W1 = (const float*)d_in[1];
    const float* W2 = (const float*)d_in[2];
    const float* W3 = (const float*)d_in[3];
    const float* G1 = (const float*)d_in[4];
    const float* G2 = (const float*)d_in[5];
    const float* G3 = (const float*)d_in[6];
    const float* Wl = (const float*)d_in[7];
    const float* bl = (const float*)d_in[8];
    float* out  = (float*)d_out;
    float* outY = out;
    float* outF = out + (size_t)NSAMP * 2;

    float *bufA, *bufB, *part, *accM, *accL, *m0s, *m0is, *gG, *gP, *ws1, *ws2, *ws3;
    cudaGetSymbolAddress((void**)&bufA, g_bufA);
    cudaGetSymbolAddress((void**)&bufB, g_bufB);
    cudaGetSymbolAddress((void**)&part, g_part);
    cudaGetSymbolAddress((void**)&accM, g_accM);
    cudaGetSymbolAddress((void**)&accL, g_accL);
    cudaGetSymbolAddress((void**)&m0s,  g_M0s);
    cudaGetSymbolAddress((void**)&m0is, g_M0is);
    cudaGetSymbolAddress((void**)&gG,   g_G);
    cudaGetSymbolAddress((void**)&gP,   g_P);
    cudaGetSymbolAddress((void**)&ws1,  g_Ws1);
    cudaGetSymbolAddress((void**)&ws2,  g_Ws2);
    cudaGetSymbolAddress((void**)&ws3,  g_Ws3);

    // sqrtm of the learned SPD biases (independent)
    ws_kernel<58><<<1, NT>>>(G1, ws1);
    ws_kernel<54><<<1, NT>>>(G2, ws2);
    ws_kernel<50><<<1, NT>>>(G3, ws3);

    // ---------------- Layer 1 (62 -> 58), curr = bufA ----------------
    {
        const int D = 58;
        const int EB = (D * D + NT - 1) / NT;
        bimap_kernel<62, 58><<<NSAMP, NT>>>(x, W1, bufA);
        red1_kernel<D><<<dim3(EB, NGRP), NT>>>(bufA, part);
        red2_kernel<D><<<1, NT>>>(part, accM);
        eig_m0_kernel<D><<<1, NT>>>(accM, m0s, m0is);
        bn_logm_kernel<D><<<NSAMP, NT>>>(bufA, m0is, bufB);
        red1_kernel<D><<<dim3(EB, NGRP), NT>>>(bufB, part);
        red2_kernel<D><<<1, NT>>>(part, accL);
        formG_kernel<D><<<1, NT>>>(accL, m0s, gG);
        eig_p_kernel<D><<<1, NT>>>(gG, ws1, gP);
        apply_reeig_kernel<D><<<NSAMP, NT>>>(bufA, gP);
    }
    // ---------------- Layer 2 (58 -> 54), curr = bufB ----------------
    {
        const int D = 54;
        const int EB = (D * D + NT - 1) / NT;
        bimap_kernel<58, 54><<<NSAMP, NT>>>(bufA, W2, bufB);
        red1_kernel<D><<<dim3(EB, NGRP), NT>>>(bufB, part);
        red2_kernel<D><<<1, NT>>>(part, accM);
        eig_m0_kernel<D><<<1, NT>>>(accM, m0s, m0is);
        bn_logm_kernel<D><<<NSAMP, NT>>>(bufB, m0is, bufA);
        red1_kernel<D><<<dim3(EB, NGRP), NT>>>(bufA, part);
        red2_kernel<D><<<1, NT>>>(part, accL);
        formG_kernel<D><<<1, NT>>>(accL, m0s, gG);
        eig_p_kernel<D><<<1, NT>>>(gG, ws2, gP);
        apply_reeig_kernel<D><<<NSAMP, NT>>>(bufB, gP);
    }
    // ---------------- Layer 3 (54 -> 50), curr = bufA ----------------
    {
        const int D = 50;
        const int EB = (D * D + NT - 1) / NT;
        bimap_kernel<54, 50><<<NSAMP, NT>>>(bufB, W3, bufA);
        red1_kernel<D><<<dim3(EB, NGRP), NT>>>(bufA, part);
        red2_kernel<D><<<1, NT>>>(part, accM);
        eig_m0_kernel<D><<<1, NT>>>(accM, m0s, m0is);
        bn_logm_kernel<D><<<NSAMP, NT>>>(bufA, m0is, bufB);
        red1_kernel<D><<<dim3(EB, NGRP), NT>>>(bufB, part);
        red2_kernel<D><<<1, NT>>>(part, accL);
        formG_kernel<D><<<1, NT>>>(accL, m0s, gG);
        eig_p_kernel<D><<<1, NT>>>(gG, ws3, gP);
        final_kernel<D><<<NSAMP, NT>>>(bufA, gP, Wl, bl, outY, outF);
    }
}

// round 4
// speedup vs baseline: 1.0955x; 1.0955x over previous
#include <cuda_runtime.h>
#include <math.h>

// ============================================================================
// RieBatchNet (SPDNet forward): BiMap -> SPD-BatchNorm -> ReEig (x2),
// BiMap -> SPD-BatchNorm -> LogEig -> Linear head.
// Batched symmetric eig via parallel cyclic Jacobi, one CTA per matrix.
// Round 4: LD=D+1 padded shared (conflict-free), congruence split out of the
// eig kernels (2-matrix smem -> 8 CTAs/SM), loosened Jacobi tolerance.
// ============================================================================

#define NT 256
#define NSAMP 8192
#define EPS_RE 1e-4f
#define NGRP 64           // reduction groups
#define SPG  (NSAMP/NGRP) // samples per group = 128

// ------------------ device scratch (static, no allocation) ------------------
__device__ float g_bufA[(size_t)NSAMP * 58 * 58];
__device__ float g_bufB[(size_t)NSAMP * 58 * 58];
__device__ float g_part[NGRP * 58 * 58];
__device__ float g_accM[58 * 58];
__device__ float g_accL[58 * 58];
__device__ float g_M0s[58 * 58];
__device__ float g_M0is[58 * 58];
__device__ float g_G[58 * 58];
__device__ float g_P[58 * 58];
__device__ float g_Ws1[58 * 58];
__device__ float g_Ws2[54 * 54];
__device__ float g_Ws3[50 * 50];

// ---------------------------------------------------------------------------
__device__ __forceinline__ float warp_sum(float v) {
#pragma unroll
    for (int o = 16; o > 0; o >>= 1) v += __shfl_xor_sync(0xffffffffu, v, o);
    return v;
}

// deterministic block reduction; all threads get the result
__device__ __forceinline__ float block_sum(float v, float* sred, int tid) {
    v = warp_sum(v);
    if ((tid & 31) == 0) sred[tid >> 5] = v;
    __syncthreads();
    if (tid == 0) {
        float t = 0.f;
#pragma unroll
        for (int w = 0; w < NT / 32; w++) t += sred[w];
        sred[8] = t;
    }
    __syncthreads();
    return sred[8];
}

// ---------------------------------------------------------------------------
// Parallel cyclic Jacobi on shared A (D x D, leading dim LD = D+1, odd ->
// all rotation accesses bank-conflict-free). V accumulates eigenvectors:
// on exit A0 = V diag(A_ii) V^T. D even. Deterministic early exit.
// ---------------------------------------------------------------------------
template <int D>
__device__ void jacobi(float* A, float* V, float* sc, float* ss_,
                       int* sp, int* sq, float* sred, int tid) {
    constexpr int LD = D + 1;
    const int m = D / 2, M = D - 1;
    // V = I
    for (int e = tid; e < D * D; e += NT) {
        int i = e / D, j = e - i * D;
        V[i * LD + j] = (i == j) ? 1.f : 0.f;
    }
    // Frobenius norm of input
    float fs = 0.f;
    for (int e = tid; e < D * D; e += NT) {
        int i = e / D, j = e - i * D;
        float v = A[i * LD + j];
        fs += v * v;
    }
    float fro2 = block_sum(fs, sred, tid);   // also syncs V init
    float skipT = 1e-10f * sqrtf(fro2);
    float tol2 = 1e-12f * fro2;

    for (int sw = 0; sw < 15; ++sw) {
        for (int r = 0; r < M; ++r) {
            if (tid < m) {
                int a, b;
                if (tid == 0) { a = M; b = r; }
                else { a = (r + tid) % M; b = (r - tid + M) % M; }
                int p = a < b ? a : b;
                int q = a < b ? b : a;
                sp[tid] = p; sq[tid] = q;
                float apq = A[p * LD + q];
                float c = 1.f, s = 0.f;
                if (fabsf(apq) > skipT) {
                    float tau = (A[q * LD + q] - A[p * LD + p]) / (2.f * apq);
                    float t = 1.f / (fabsf(tau) + sqrtf(1.f + tau * tau));
                    t = (tau >= 0.f) ? t : -t;
                    c = 1.f / sqrtf(1.f + t * t);
                    s = t * c;
                }
                sc[tid] = c; ss_[tid] = s;
            }
            __syncthreads();
            // column rotations: A <- A*J, V <- V*J (disjoint column pairs).
            // consecutive lanes -> consecutive rows i, stride LD (odd) -> CF.
            for (int e = tid; e < D * m; e += NT) {
                int k = e / D;
                int i = e - k * D;
                float s = ss_[k];
                if (s != 0.f) {
                    float c = sc[k];
                    int p = sp[k], q = sq[k];
                    float x = A[i * LD + p], y = A[i * LD + q];
                    A[i * LD + p] = c * x - s * y;
                    A[i * LD + q] = s * x + c * y;
                    x = V[i * LD + p]; y = V[i * LD + q];
                    V[i * LD + p] = c * x - s * y;
                    V[i * LD + q] = s * x + c * y;
                }
            }
            __syncthreads();
            // row rotations: A <- J^T * A (disjoint row pairs).
            // consecutive lanes -> consecutive cols j -> CF.
            for (int e = tid; e < D * m; e += NT) {
                int k = e / D;
                int j = e - k * D;
                float s = ss_[k];
                if (s != 0.f) {
                    float c = sc[k];
                    int p = sp[k], q = sq[k];
                    float x = A[p * LD + j], y = A[q * LD + j];
                    A[p * LD + j] = c * x - s * y;
                    A[q * LD + j] = s * x + c * y;
                }
            }
            __syncthreads();
        }
        float off = 0.f;
        for (int e = tid; e < D * D; e += NT) {
            int i = e / D, j = e - i * D;
            if (i != j) { float v = A[i * LD + j]; off += v * v; }
        }
        if (block_sum(off, sred, tid) <= tol2) break;
    }
    __syncthreads();
}

// ---------------------------------------------------------------------------
// BiMap: Y_n = W X_n W^T   (W: Dout x Din). Padded W/T tiles (LDW odd -> CF).
// ---------------------------------------------------------------------------
template <int Din, int Dout>
__global__ void __launch_bounds__(NT)
bimap_kernel(const float* __restrict__ X,
             const float* __restrict__ W,
             float* __restrict__ Y) {
    constexpr int LDW = Din + 1;
    __shared__ float sX[Din * Din];
    __shared__ float sW[Dout * LDW];
    __shared__ float sT[Dout * LDW];
    int tid = threadIdx.x;
    size_t n = blockIdx.x;
    const float* Xn = X + n * Din * Din;
    for (int e = tid; e < Din * Din; e += NT) sX[e] = Xn[e];
    for (int e = tid; e < Dout * Din; e += NT) {
        int i = e / Din, k = e - i * Din;
        sW[i * LDW + k] = W[e];
    }
    __syncthreads();
    for (int e = tid; e < Dout * Din; e += NT) {
        int i = e / Din, j = e - i * Din;
        float acc = 0.f;
#pragma unroll 4
        for (int k = 0; k < Din; k++) acc += sW[i * LDW + k] * sX[k * Din + j];
        sT[i * LDW + j] = acc;
    }
    __syncthreads();
    float* Yn = Y + n * Dout * Dout;
    for (int e = tid; e < Dout * Dout; e += NT) {
        int i = e / Dout, j = e - i * Dout;
        float acc = 0.f;
#pragma unroll 4
        for (int k = 0; k < Din; k++) acc += sT[i * LDW + k] * sW[j * LDW + k];
        Yn[e] = acc;
    }
}

// ---------------------------------------------------------------------------
// Congruence: Y_n = sym(P X_n P^T). P is a single D x D matrix.
// ---------------------------------------------------------------------------
template <int D>
__global__ void __launch_bounds__(NT)
congr_kernel(const float* __restrict__ X,
             const float* __restrict__ P,
             float* __restrict__ Y) {
    constexpr int LD = D + 1;
    __shared__ float sX[D * LD];
    __shared__ float sP[D * LD];
    __shared__ float sT[D * LD];
    int tid = threadIdx.x;
    size_t n = blockIdx.x;
    const float* Xn = X + n * D * D;
    for (int e = tid; e < D * D; e += NT) {
        int i = e / D, j = e - i * D;
        sX[i * LD + j] = Xn[e];
        sP[i * LD + j] = P[e];
    }
    __syncthreads();
    // T = P @ X
    for (int e = tid; e < D * D; e += NT) {
        int i = e / D, j = e - i * D;
        float acc = 0.f;
#pragma unroll 4
        for (int k = 0; k < D; k++) acc += sP[i * LD + k] * sX[k * LD + j];
        sT[i * LD + j] = acc;
    }
    __syncthreads();
    // R = T @ P^T -> overwrite sX
    for (int e = tid; e < D * D; e += NT) {
        int i = e / D, j = e - i * D;
        float acc = 0.f;
#pragma unroll 4
        for (int k = 0; k < D; k++) acc += sT[i * LD + k] * sP[j * LD + k];
        sX[i * LD + j] = acc;   // safe: sX fully consumed before this sync point
    }
    __syncthreads();
    float* Yn = Y + n * D * D;
    for (int e = tid; e < D * D; e += NT) {
        int i = e / D, j = e - i * D;
        Yn[e] = 0.5f * (sX[i * LD + j] + sX[j * LD + i]);
    }
}

// ---------------------------------------------------------------------------
// Batch-mean reduction (deterministic two stage). red2 scales by 1/NSAMP and
// symmetrizes.
// ---------------------------------------------------------------------------
template <int D>
__global__ void __launch_bounds__(NT)
red1_kernel(const float* __restrict__ src, float* __restrict__ part) {
    int e = blockIdx.x * NT + threadIdx.x;
    int g = blockIdx.y;
    if (e >= D * D) return;
    float s = 0.f;
    const float* p = src + (size_t)g * SPG * D * D + e;
    for (int i = 0; i < SPG; i++) s += p[(size_t)i * D * D];
    part[g * D * D + e] = s;
}

template <int D>
__global__ void __launch_bounds__(NT)
red2_kernel(const float* __restrict__ part, float* __restrict__ dst) {
    __shared__ float Msh[D * D];
    int tid = threadIdx.x;
    for (int e = tid; e < D * D; e += NT) {
        float s = 0.f;
        for (int g = 0; g < NGRP; g++) s += part[g * D * D + e];
        Msh[e] = s * (1.f / (float)NSAMP);
    }
    __syncthreads();
    for (int e = tid; e < D * D; e += NT) {
        int i = e / D, j = e - i * D;
        dst[e] = 0.5f * (Msh[e] + Msh[j * D + i]);
    }
}

// ---------------------------------------------------------------------------
// Single-matrix eig kernels (1 block each). Padded shared.
// ---------------------------------------------------------------------------
#define EIG_DECL(D)                                              \
    constexpr int LD = (D) + 1;                                  \
    __shared__ float U0[(D) * LD]; __shared__ float U2[(D) * LD]; \
    __shared__ float sc[(D) / 2]; __shared__ float ssn[(D) / 2];  \
    __shared__ int sp[(D) / 2]; __shared__ int sq[(D) / 2];       \
    __shared__ float sred[9]; __shared__ float sf[(D)];           \
    int tid = threadIdx.x;

// Ws = sqrtm(sym(Gw))
template <int D>
__global__ void __launch_bounds__(NT)
ws_kernel(const float* __restrict__ Gw, float* __restrict__ Ws) {
    EIG_DECL(D)
    for (int e = tid; e < D * D; e += NT) {
        int i = e / D, j = e - i * D;
        U0[i * LD + j] = 0.5f * (Gw[e] + Gw[j * D + i]);
    }
    __syncthreads();
    jacobi<D>(U0, U2, sc, ssn, sp, sq, sred, tid);
    for (int k = tid; k < D; k += NT) sf[k] = sqrtf(fmaxf(U0[k * LD + k], 0.f));
    __syncthreads();
    for (int e = tid; e < D * D; e += NT) {
        int i = e / D, j = e - i * D;
        float acc = 0.f;
#pragma unroll 4
        for (int k = 0; k < D; k++) acc += U2[i * LD + k] * sf[k] * U2[j * LD + k];
        Ws[e] = acc;
    }
}

// M0s = sqrtm(M0), M0is = isqrtm(M0)
template <int D>
__global__ void __launch_bounds__(NT)
eig_m0_kernel(const float* __restrict__ M0,
              float* __restrict__ M0s, float* __restrict__ M0is) {
    EIG_DECL(D)
    for (int e = tid; e < D * D; e += NT) {
        int i = e / D, j = e - i * D;
        U0[i * LD + j] = M0[e];
    }
    __syncthreads();
    jacobi<D>(U0, U2, sc, ssn, sp, sq, sred, tid);
    for (int k = tid; k < D; k += NT) sf[k] = sqrtf(fmaxf(U0[k * LD + k], 1e-30f));
    __syncthreads();
    for (int e = tid; e < D * D; e += NT) {
        int i = e / D, j = e - i * D;
        float acc = 0.f;
#pragma unroll 4
        for (int k = 0; k < D; k++) acc += U2[i * LD + k] * sf[k] * U2[j * LD + k];
        M0s[e] = acc;
    }
    __syncthreads();
    for (int k = tid; k < D; k += NT) sf[k] = 1.f / sf[k];
    __syncthreads();
    for (int e = tid; e < D * D; e += NT) {
        int i = e / D, j = e - i * D;
        float acc = 0.f;
#pragma unroll 4
        for (int k = 0; k < D; k++) acc += U2[i * LD + k] * sf[k] * U2[j * LD + k];
        M0is[e] = acc;
    }
}

// G = sym(M0s expm(L) M0s)
template <int D>
__global__ void __launch_bounds__(NT)
formG_kernel(const float* __restrict__ L,
             const float* __restrict__ M0s, float* __restrict__ G) {
    EIG_DECL(D)
    __shared__ float U1[D * LD];
    for (int e = tid; e < D * D; e += NT) {
        int i = e / D, j = e - i * D;
        U0[i * LD + j] = L[e];
        U1[i * LD + j] = M0s[e];
    }
    __syncthreads();
    jacobi<D>(U0, U2, sc, ssn, sp, sq, sred, tid);
    for (int k = tid; k < D; k += NT) sf[k] = expf(U0[k * LD + k]);
    __syncthreads();
    // E = V exp V^T -> U0
    {
        float tmp[(D * D + NT - 1) / NT];
        int c = 0;
        for (int e = tid; e < D * D; e += NT) {
            int i = e / D, j = e - i * D;
            float acc = 0.f;
#pragma unroll 4
            for (int k = 0; k < D; k++) acc += U2[i * LD + k] * sf[k] * U2[j * LD + k];
            tmp[c++] = acc;
        }
        __syncthreads();
        c = 0;
        for (int e = tid; e < D * D; e += NT) {
            int i = e / D, j = e - i * D;
            U0[i * LD + j] = tmp[c++];
        }
        __syncthreads();
    }
    // T = M0s @ E -> U2
    for (int e = tid; e < D * D; e += NT) {
        int i = e / D, j = e - i * D;
        float acc = 0.f;
#pragma unroll 4
        for (int k = 0; k < D; k++) acc += U1[i * LD + k] * U0[k * LD + j];
        U2[i * LD + j] = acc;
    }
    __syncthreads();
    // G = sym(T @ M0s)
    {
        float tmp[(D * D + NT - 1) / NT];
        int c = 0;
        for (int e = tid; e < D * D; e += NT) {
            int i = e / D, j = e - i * D;
            float acc = 0.f;
#pragma unroll 4
            for (int k = 0; k < D; k++) acc += U2[i * LD + k] * U1[k * LD + j];
            tmp[c++] = acc;
        }
        __syncthreads();
        c = 0;
        for (int e = tid; e < D * D; e += NT) {
            int i = e / D, j = e - i * D;
            U0[i * LD + j] = tmp[c++];
        }
        __syncthreads();
        for (int e = tid; e < D * D; e += NT) {
            int i = e / D, j = e - i * D;
            G[e] = 0.5f * (U0[i * LD + j] + U0[j * LD + i]);
        }
    }
}

// P = Ws @ isqrtm(G)
template <int D>
__global__ void __launch_bounds__(NT)
eig_p_kernel(const float* __restrict__ G,
             const float* __restrict__ Ws, float* __restrict__ P) {
    EIG_DECL(D)
    __shared__ float U1[D * LD];
    for (int e = tid; e < D * D; e += NT) {
        int i = e / D, j = e - i * D;
        U0[i * LD + j] = G[e];
        U1[i * LD + j] = Ws[e];
    }
    __syncthreads();
    jacobi<D>(U0, U2, sc, ssn, sp, sq, sred, tid);
    for (int k = tid; k < D; k += NT)
        sf[k] = 1.f / sqrtf(fmaxf(U0[k * LD + k], 1e-30f));
    __syncthreads();
    // Gis = V f V^T -> U0
    {
        float tmp[(D * D + NT - 1) / NT];
        int c = 0;
        for (int e = tid; e < D * D; e += NT) {
            int i = e / D, j = e - i * D;
            float acc = 0.f;
#pragma unroll 4
            for (int k = 0; k < D; k++) acc += U2[i * LD + k] * sf[k] * U2[j * LD + k];
            tmp[c++] = acc;
        }
        __syncthreads();
        c = 0;
        for (int e = tid; e < D * D; e += NT) {
            int i = e / D, j = e - i * D;
            U0[i * LD + j] = tmp[c++];
        }
        __syncthreads();
    }
    // P = Ws @ Gis
    for (int e = tid; e < D * D; e += NT) {
        int i = e / D, j = e - i * D;
        float acc = 0.f;
#pragma unroll 4
        for (int k = 0; k < D; k++) acc += U1[i * LD + k] * U0[k * LD + j];
        P[e] = acc;
    }
}

// ---------------------------------------------------------------------------
// Batched eig-function kernels: only 2 padded matrices in shared (~28 KB at
// D=58) -> 8 CTAs/SM. Input B (symmetric) read from global; output written
// in place (safe: B fully staged to shared before any write).
// ---------------------------------------------------------------------------
// Z = logm(B), in place
template <int D>
__global__ void __launch_bounds__(NT, 8)
eig_log_kernel(float* __restrict__ B) {
    EIG_DECL(D)
    size_t n = blockIdx.x;
    float* Bn = B + n * D * D;
    for (int e = tid; e < D * D; e += NT) {
        int i = e / D, j = e - i * D;
        U0[i * LD + j] = Bn[e];
    }
    __syncthreads();
    jacobi<D>(U0, U2, sc, ssn, sp, sq, sred, tid);
    for (int k = tid; k < D; k += NT)
        sf[k] = logf(fmaxf(U0[k * LD + k], 1e-30f));
    __syncthreads();
    for (int e = tid; e < D * D; e += NT) {
        int i = e / D, j = e - i * D;
        float acc = 0.f;
#pragma unroll 4
        for (int k = 0; k < D; k++) acc += U2[i * LD + k] * sf[k] * U2[j * LD + k];
        Bn[e] = acc;
    }
}

// B <- ReEig(B) = U max(lam, eps) U^T, in place
template <int D>
__global__ void __launch_bounds__(NT, 8)
eig_clamp_kernel(float* __restrict__ B) {
    EIG_DECL(D)
    size_t n = blockIdx.x;
    float* Bn = B + n * D * D;
    for (int e = tid; e < D * D; e += NT) {
        int i = e / D, j = e - i * D;
        U0[i * LD + j] = Bn[e];
    }
    __syncthreads();
    jacobi<D>(U0, U2, sc, ssn, sp, sq, sred, tid);
    for (int k = tid; k < D; k += NT)
        sf[k] = fmaxf(U0[k * LD + k], EPS_RE);
    __syncthreads();
    for (int e = tid; e < D * D; e += NT) {
        int i = e / D, j = e - i * D;
        float acc = 0.f;
#pragma unroll 4
        for (int k = 0; k < D; k++) acc += U2[i * LD + k] * sf[k] * U2[j * LD + k];
        Bn[e] = acc;
    }
}

// y = vec(logm(F)) @ Wl^T + bl    (F = feat, already in d_out; not modified)
template <int D>
__global__ void __launch_bounds__(NT, 8)
eig_y_kernel(const float* __restrict__ F,
             const float* __restrict__ Wl, const float* __restrict__ bl,
             float* __restrict__ outY) {
    EIG_DECL(D)
    size_t n = blockIdx.x;
    const float* Fn = F + n * D * D;
    for (int e = tid; e < D * D; e += NT) {
        int i = e / D, j = e - i * D;
        U0[i * LD + j] = Fn[e];
    }
    __syncthreads();
    jacobi<D>(U0, U2, sc, ssn, sp, sq, sred, tid);
    for (int k = tid; k < D; k += NT)
        sf[k] = logf(fmaxf(U0[k * LD + k], 1e-30f));
    __syncthreads();
    float y0 = 0.f, y1 = 0.f;
    for (int e = tid; e < D * D; e += NT) {
        int i = e / D, j = e - i * D;
        float acc = 0.f;
#pragma unroll 4
        for (int k = 0; k < D; k++) acc += U2[i * LD + k] * sf[k] * U2[j * LD + k];
        y0 += acc * Wl[e];
        y1 += acc * Wl[D * D + e];
    }
    y0 = block_sum(y0, sred, tid);
    y1 = block_sum(y1, sred, tid);
    if (tid == 0) {
        outY[n * 2 + 0] = y0 + bl[0];
        outY[n * 2 + 1] = y1 + bl[1];
    }
}

// ---------------------------------------------------------------------------
extern "C" void kernel_launch(void* const* d_in, const int* in_sizes, int n_in,
                              void* d_out, int out_size) {
    (void)in_sizes; (void)n_in; (void)out_size;
    const float* x  = (const float*)d_in[0];
    const float* W1 = (const float*)d_in[1];
    const float* W2 = (const float*)d_in[2];
    const float* W3 = (const float*)d_in[3];
    const float* G1 = (const float*)d_in[4];
    const float* G2 = (const float*)d_in[5];
    const float* G3 = (const float*)d_in[6];
    const float* Wl = (const float*)d_in[7];
    const float* bl = (const float*)d_in[8];
    float* out  = (float*)d_out;
    float* outY = out;
    float* outF = out + (size_t)NSAMP * 2;

    float *bufA, *bufB, *part, *accM, *accL, *m0s, *m0is, *gG, *gP, *ws1, *ws2, *ws3;
    cudaGetSymbolAddress((void**)&bufA, g_bufA);
    cudaGetSymbolAddress((void**)&bufB, g_bufB);
    cudaGetSymbolAddress((void**)&part, g_part);
    cudaGetSymbolAddress((void**)&accM, g_accM);
    cudaGetSymbolAddress((void**)&accL, g_accL);
    cudaGetSymbolAddress((void**)&m0s,  g_M0s);
    cudaGetSymbolAddress((void**)&m0is, g_M0is);
    cudaGetSymbolAddress((void**)&gG,   g_G);
    cudaGetSymbolAddress((void**)&gP,   g_P);
    cudaGetSymbolAddress((void**)&ws1,  g_Ws1);
    cudaGetSymbolAddress((void**)&ws2,  g_Ws2);
    cudaGetSymbolAddress((void**)&ws3,  g_Ws3);

    // sqrtm of the learned SPD biases (independent)
    ws_kernel<58><<<1, NT>>>(G1, ws1);
    ws_kernel<54><<<1, NT>>>(G2, ws2);
    ws_kernel<50><<<1, NT>>>(G3, ws3);

    // ---------------- Layer 1 (62 -> 58): curr in bufA ----------------
    {
        const int D = 58;
        const int EB = (D * D + NT - 1) / NT;
        bimap_kernel<62, 58><<<NSAMP, NT>>>(x, W1, bufA);
        red1_kernel<D><<<dim3(EB, NGRP), NT>>>(bufA, part);
        red2_kernel<D><<<1, NT>>>(part, accM);
        eig_m0_kernel<D><<<1, NT>>>(accM, m0s, m0is);
        congr_kernel<D><<<NSAMP, NT>>>(bufA, m0is, bufB);   // B = sym(M0is X M0is)
        eig_log_kernel<D><<<NSAMP, NT>>>(bufB);             // B <- logm(B)
        red1_kernel<D><<<dim3(EB, NGRP), NT>>>(bufB, part);
        red2_kernel<D><<<1, NT>>>(part, accL);
        formG_kernel<D><<<1, NT>>>(accL, m0s, gG);
        eig_p_kernel<D><<<1, NT>>>(gG, ws1, gP);
        congr_kernel<D><<<NSAMP, NT>>>(bufA, gP, bufB);     // B = sym(P X P^T)
        eig_clamp_kernel<D><<<NSAMP, NT>>>(bufB);           // B <- ReEig(B)
    }
    // ---------------- Layer 2 (58 -> 54): curr in bufB ----------------
    {
        const int D = 54;
        const int EB = (D * D + NT - 1) / NT;
        bimap_kernel<58, 54><<<NSAMP, NT>>>(bufB, W2, bufA);
        red1_kernel<D><<<dim3(EB, NGRP), NT>>>(bufA, part);
        red2_kernel<D><<<1, NT>>>(part, accM);
        eig_m0_kernel<D><<<1, NT>>>(accM, m0s, m0is);
        congr_kernel<D><<<NSAMP, NT>>>(bufA, m0is, bufB);
        eig_log_kernel<D><<<NSAMP, NT>>>(bufB);
        red1_kernel<D><<<dim3(EB, NGRP), NT>>>(bufB, part);
        red2_kernel<D><<<1, NT>>>(part, accL);
        formG_kernel<D><<<1, NT>>>(accL, m0s, gG);
        eig_p_kernel<D><<<1, NT>>>(gG, ws2, gP);
        congr_kernel<D><<<NSAMP, NT>>>(bufA, gP, bufB);
        eig_clamp_kernel<D><<<NSAMP, NT>>>(bufB);
    }
    // ---------------- Layer 3 (54 -> 50): curr in bufB ----------------
    {
        const int D = 50;
        const int EB = (D * D + NT - 1) / NT;
        bimap_kernel<54, 50><<<NSAMP, NT>>>(bufB, W3, bufA);
        red1_kernel<D><<<dim3(EB, NGRP), NT>>>(bufA, part);
        red2_kernel<D><<<1, NT>>>(part, accM);
        eig_m0_kernel<D><<<1, NT>>>(accM, m0s, m0is);
        congr_kernel<D><<<NSAMP, NT>>>(bufA, m0is, bufB);
        eig_log_kernel<D><<<NSAMP, NT>>>(bufB);
        red1_kernel<D><<<dim3(EB, NGRP), NT>>>(bufB, part);
        red2_kernel<D><<<1, NT>>>(part, accL);
        formG_kernel<D><<<1, NT>>>(accL, m0s, gG);
        eig_p_kernel<D><<<1, NT>>>(gG, ws3, gP);
        congr_kernel<D><<<NSAMP, NT>>>(bufA, gP, outF);     // feat -> d_out
        eig_y_kernel<D><<<NSAMP, NT>>>(outF, Wl, bl, outY); // y -> d_out
    }
}

// round 7
// speedup vs baseline: 1.7006x; 1.5524x over previous
#include <cuda_runtime.h>
#include <math.h>

// ============================================================================
// RieBatchNet (SPDNet forward): BiMap -> SPD-BatchNorm -> ReEig (x2),
// BiMap -> SPD-BatchNorm -> LogEig -> Linear head.
// Round 7 (= Round 6 re-land; R6 never executed due to infra failure):
// batched SPD eigs use ONE-SIDED Hestenes Jacobi (no V matrix, no row phase,
// 1 sync/round, register-cached float2 columns, 8-lane-group shfl masks).
// Single-matrix kernels (incl. indefinite expm path) keep the two-sided engine.
// ============================================================================

#define NT 256
#define NSAMP 8192
#define EPS_RE 1e-4f
#define NGRP 64           // reduction groups
#define SPG  (NSAMP/NGRP) // samples per group = 128

// ------------------ device scratch (static, no allocation) ------------------
__device__ float g_bufA[(size_t)NSAMP * 58 * 58];
__device__ float g_bufB[(size_t)NSAMP * 58 * 58];
__device__ float g_part[NGRP * 58 * 58];
__device__ float g_accM[58 * 58];
__device__ float g_accL[58 * 58];
__device__ float g_M0s[58 * 58];
__device__ float g_M0is[58 * 58];
__device__ float g_G[58 * 58];
__device__ float g_P[58 * 58];
__device__ float g_Ws1[58 * 58];
__device__ float g_Ws2[54 * 54];
__device__ float g_Ws3[50 * 50];

// ---------------------------------------------------------------------------
__device__ __forceinline__ float warp_sum(float v) {
#pragma unroll
    for (int o = 16; o > 0; o >>= 1) v += __shfl_xor_sync(0xffffffffu, v, o);
    return v;
}

// deterministic block reduction; all threads get the result
__device__ __forceinline__ float block_sum(float v, float* sred, int tid) {
    v = warp_sum(v);
    if ((tid & 31) == 0) sred[tid >> 5] = v;
    __syncthreads();
    if (tid == 0) {
        float t = 0.f;
#pragma unroll
        for (int w = 0; w < NT / 32; w++) t += sred[w];
        sred[8] = t;
    }
    __syncthreads();
    return sred[8];
}

// ===========================================================================
// ONE-SIDED Hestenes Jacobi for SPD matrices (batched path).
// G (column-major, LD = D+4) starts as A. At convergence column k = lam_k v_k,
// so f(A) = sum_k (f(s_k)/s_k^2) g_k g_k^T with s_k = |g_k|.
// 8 lanes per column pair; columns cached in registers between dot and rotate.
// One __syncthreads per round. Shfl masks cover ONLY the 8-lane group
// (group-uniform branch -> every lane named in the mask reaches the shfl).
// ===========================================================================
template <int D>
__device__ __forceinline__ void jacobi1s(float* G, int* s_any, int tid) {
    constexpr int LD = D + 4;
    constexpr int m = D / 2;
    constexpr int M = D - 1;
    constexpr int NH = D / 2;               // float2 elements per column
    constexpr int UMAX = (NH + 7) / 8;      // <= 4 register-cached float2 each
    const int grp = tid >> 3;
    const int lane = tid & 7;
    const unsigned mask8 = 0xffu << ((tid & 31) & ~7);   // this thread's 8-lane group

    for (int sw = 0; sw < 12; ++sw) {
        for (int r = 0; r < M; ++r) {
            if (grp < m) {
                int p, q;
                if (grp == 0) { p = r; q = M; }
                else {
                    int a = (r + grp) % M;
                    int b = (r - grp + M) % M;
                    p = a < b ? a : b;
                    q = a < b ? b : a;
                }
                float2* Gp = (float2*)(G + p * LD);
                float2* Gq = (float2*)(G + q * LD);
                float app = 0.f, aqq = 0.f, apq = 0.f;
                float2 rp[UMAX], rq[UMAX];
                int h = lane;
#pragma unroll
                for (int u = 0; u < UMAX; ++u) {
                    if (h < NH) {
                        float2 xp = Gp[h], xq = Gq[h];
                        rp[u] = xp; rq[u] = xq;
                        app = fmaf(xp.x, xp.x, fmaf(xp.y, xp.y, app));
                        aqq = fmaf(xq.x, xq.x, fmaf(xq.y, xq.y, aqq));
                        apq = fmaf(xp.x, xq.x, fmaf(xp.y, xq.y, apq));
                    }
                    h += 8;
                }
#pragma unroll
                for (int o = 4; o > 0; o >>= 1) {
                    app += __shfl_xor_sync(mask8, app, o);
                    aqq += __shfl_xor_sync(mask8, aqq, o);
                    apq += __shfl_xor_sync(mask8, apq, o);
                }
                if (apq * apq > 4e-14f * app * aqq) {
                    float tau = (aqq - app) / (2.f * apq);
                    float t = 1.f / (fabsf(tau) + sqrtf(1.f + tau * tau));
                    t = (tau >= 0.f) ? t : -t;
                    float c = rsqrtf(1.f + t * t);
                    float s = t * c;
                    h = lane;
#pragma unroll
                    for (int u = 0; u < UMAX; ++u) {
                        if (h < NH) {
                            float2 xp = rp[u], xq = rq[u];
                            Gp[h] = make_float2(fmaf(c, xp.x, -s * xq.x),
                                                fmaf(c, xp.y, -s * xq.y));
                            Gq[h] = make_float2(fmaf(s, xp.x, c * xq.x),
                                                fmaf(s, xp.y, c * xq.y));
                        }
                        h += 8;
                    }
                    if (lane == 0) *s_any = 1;   // benign constant-write race
                }
            }
            __syncthreads();
        }
        int any = *s_any;
        __syncthreads();
        if (tid == 0) *s_any = 0;
        __syncthreads();
        if (!any) break;
    }
}

// Per-column squared norms -> weights sf[k] = f(sqrt(nr)) / nr.
// MODE 0: log, MODE 1: clamp(EPS_RE)
template <int D, int MODE>
__device__ __forceinline__ void col_weights(const float* G, float* sf, int tid) {
    constexpr int LD = D + 4;
    constexpr int NH = D / 2;
    if (tid < D) {
        const float2* gc = (const float2*)(G + tid * LD);
        float nr = 0.f;
#pragma unroll
        for (int h0 = 0; h0 < NH; ++h0)
            nr = fmaf(gc[h0].x, gc[h0].x, fmaf(gc[h0].y, gc[h0].y, nr));
        nr = fmaxf(nr, 1e-30f);
        float w;
        if (MODE == 0) w = (0.5f * logf(nr)) / nr;
        else           w = fmaxf(sqrtf(nr), EPS_RE) / nr;
        sf[tid] = w;
    }
    __syncthreads();
}

// ---------------------------------------------------------------------------
// Batched eig-function kernels (one-sided engine).
// ---------------------------------------------------------------------------
template <int D>
__global__ void __launch_bounds__(NT, 8)
eig_log_kernel(float* __restrict__ B) {
    constexpr int LD = D + 4;
    __shared__ float G[D * LD];
    __shared__ float sf[D];
    __shared__ int s_any;
    int tid = threadIdx.x;
    size_t n = blockIdx.x;
    float* Bn = B + n * D * D;
    if (tid == 0) s_any = 0;
    for (int e = tid; e < D * D; e += NT) {
        int c = e / D, r0 = e - c * D;
        G[c * LD + r0] = Bn[e];         // symmetric: col-major == row-major
    }
    __syncthreads();
    jacobi1s<D>(G, &s_any, tid);
    col_weights<D, 0>(G, sf, tid);
    for (int e = tid; e < D * D; e += NT) {
        int i = e / D, j = e - i * D;
        float acc = 0.f;
#pragma unroll 4
        for (int k = 0; k < D; k++)
            acc = fmaf(sf[k] * G[k * LD + i], G[k * LD + j], acc);
        Bn[e] = acc;
    }
}

template <int D>
__global__ void __launch_bounds__(NT, 8)
eig_clamp_kernel(float* __restrict__ B) {
    constexpr int LD = D + 4;
    __shared__ float G[D * LD];
    __shared__ float sf[D];
    __shared__ int s_any;
    int tid = threadIdx.x;
    size_t n = blockIdx.x;
    float* Bn = B + n * D * D;
    if (tid == 0) s_any = 0;
    for (int e = tid; e < D * D; e += NT) {
        int c = e / D, r0 = e - c * D;
        G[c * LD + r0] = Bn[e];
    }
    __syncthreads();
    jacobi1s<D>(G, &s_any, tid);
    col_weights<D, 1>(G, sf, tid);
    for (int e = tid; e < D * D; e += NT) {
        int i = e / D, j = e - i * D;
        float acc = 0.f;
#pragma unroll 4
        for (int k = 0; k < D; k++)
            acc = fmaf(sf[k] * G[k * LD + i], G[k * LD + j], acc);
        Bn[e] = acc;
    }
}

// y = vec(logm(F)) @ Wl^T + bl   (F = feat, already in d_out; not modified)
template <int D>
__global__ void __launch_bounds__(NT, 8)
eig_y_kernel(const float* __restrict__ F,
             const float* __restrict__ Wl, const float* __restrict__ bl,
             float* __restrict__ outY) {
    constexpr int LD = D + 4;
    __shared__ float G[D * LD];
    __shared__ float sf[D];
    __shared__ float sred[9];
    __shared__ int s_any;
    int tid = threadIdx.x;
    size_t n = blockIdx.x;
    const float* Fn = F + n * D * D;
    if (tid == 0) s_any = 0;
    for (int e = tid; e < D * D; e += NT) {
        int c = e / D, r0 = e - c * D;
        G[c * LD + r0] = Fn[e];
    }
    __syncthreads();
    jacobi1s<D>(G, &s_any, tid);
    col_weights<D, 0>(G, sf, tid);
    float y0 = 0.f, y1 = 0.f;
    for (int e = tid; e < D * D; e += NT) {
        int i = e / D, j = e - i * D;
        float acc = 0.f;
#pragma unroll 4
        for (int k = 0; k < D; k++)
            acc = fmaf(sf[k] * G[k * LD + i], G[k * LD + j], acc);
        y0 = fmaf(acc, Wl[e], y0);
        y1 = fmaf(acc, Wl[D * D + e], y1);
    }
    y0 = block_sum(y0, sred, tid);
    y1 = block_sum(y1, sred, tid);
    if (tid == 0) {
        outY[n * 2 + 0] = y0 + bl[0];
        outY[n * 2 + 1] = y1 + bl[1];
    }
}

// ===========================================================================
// TWO-SIDED Jacobi (handles indefinite matrices) -- single-matrix kernels.
// ===========================================================================
template <int D>
__device__ void jacobi(float* A, float* V, float* sc, float* ss_,
                       int* sp, int* sq, float* sred, int tid) {
    constexpr int LD = D + 1;
    const int m = D / 2, M = D - 1;
    for (int e = tid; e < D * D; e += NT) {
        int i = e / D, j = e - i * D;
        V[i * LD + j] = (i == j) ? 1.f : 0.f;
    }
    float fs = 0.f;
    for (int e = tid; e < D * D; e += NT) {
        int i = e / D, j = e - i * D;
        float v = A[i * LD + j];
        fs += v * v;
    }
    float fro2 = block_sum(fs, sred, tid);
    float skipT = 1e-10f * sqrtf(fro2);
    float tol2 = 1e-12f * fro2;

    for (int sw = 0; sw < 15; ++sw) {
        for (int r = 0; r < M; ++r) {
            if (tid < m) {
                int a, b;
                if (tid == 0) { a = M; b = r; }
                else { a = (r + tid) % M; b = (r - tid + M) % M; }
                int p = a < b ? a : b;
                int q = a < b ? b : a;
                sp[tid] = p; sq[tid] = q;
                float apq = A[p * LD + q];
                float c = 1.f, s = 0.f;
                if (fabsf(apq) > skipT) {
                    float tau = (A[q * LD + q] - A[p * LD + p]) / (2.f * apq);
                    float t = 1.f / (fabsf(tau) + sqrtf(1.f + tau * tau));
                    t = (tau >= 0.f) ? t : -t;
                    c = 1.f / sqrtf(1.f + t * t);
                    s = t * c;
                }
                sc[tid] = c; ss_[tid] = s;
            }
            __syncthreads();
            for (int e = tid; e < D * m; e += NT) {
                int k = e / D;
                int i = e - k * D;
                float s = ss_[k];
                if (s != 0.f) {
                    float c = sc[k];
                    int p = sp[k], q = sq[k];
                    float x = A[i * LD + p], y = A[i * LD + q];
                    A[i * LD + p] = c * x - s * y;
                    A[i * LD + q] = s * x + c * y;
                    x = V[i * LD + p]; y = V[i * LD + q];
                    V[i * LD + p] = c * x - s * y;
                    V[i * LD + q] = s * x + c * y;
                }
            }
            __syncthreads();
            for (int e = tid; e < D * m; e += NT) {
                int k = e / D;
                int j = e - k * D;
                float s = ss_[k];
                if (s != 0.f) {
                    float c = sc[k];
                    int p = sp[k], q = sq[k];
                    float x = A[p * LD + j], y = A[q * LD + j];
                    A[p * LD + j] = c * x - s * y;
                    A[q * LD + j] = s * x + c * y;
                }
            }
            __syncthreads();
        }
        float off = 0.f;
        for (int e = tid; e < D * D; e += NT) {
            int i = e / D, j = e - i * D;
            if (i != j) { float v = A[i * LD + j]; off += v * v; }
        }
        if (block_sum(off, sred, tid) <= tol2) break;
    }
    __syncthreads();
}

// ---------------------------------------------------------------------------
// BiMap: Y_n = W X_n W^T   (W: Dout x Din)
// ---------------------------------------------------------------------------
template <int Din, int Dout>
__global__ void __launch_bounds__(NT)
bimap_kernel(const float* __restrict__ X,
             const float* __restrict__ W,
             float* __restrict__ Y) {
    constexpr int LDW = Din + 1;
    __shared__ float sX[Din * Din];
    __shared__ float sW[Dout * LDW];
    __shared__ float sT[Dout * LDW];
    int tid = threadIdx.x;
    size_t n = blockIdx.x;
    const float* Xn = X + n * Din * Din;
    for (int e = tid; e < Din * Din; e += NT) sX[e] = Xn[e];
    for (int e = tid; e < Dout * Din; e += NT) {
        int i = e / Din, k = e - i * Din;
        sW[i * LDW + k] = W[e];
    }
    __syncthreads();
    for (int e = tid; e < Dout * Din; e += NT) {
        int i = e / Din, j = e - i * Din;
        float acc = 0.f;
#pragma unroll 4
        for (int k = 0; k < Din; k++) acc += sW[i * LDW + k] * sX[k * Din + j];
        sT[i * LDW + j] = acc;
    }
    __syncthreads();
    float* Yn = Y + n * Dout * Dout;
    for (int e = tid; e < Dout * Dout; e += NT) {
        int i = e / Dout, j = e - i * Dout;
        float acc = 0.f;
#pragma unroll 4
        for (int k = 0; k < Din; k++) acc += sT[i * LDW + k] * sW[j * LDW + k];
        Yn[e] = acc;
    }
}

// ---------------------------------------------------------------------------
// Congruence: Y_n = sym(P X_n P^T). P is a single D x D matrix.
// ---------------------------------------------------------------------------
template <int D>
__global__ void __launch_bounds__(NT)
congr_kernel(const float* __restrict__ X,
             const float* __restrict__ P,
             float* __restrict__ Y) {
    constexpr int LD = D + 1;
    __shared__ float sX[D * LD];
    __shared__ float sP[D * LD];
    __shared__ float sT[D * LD];
    int tid = threadIdx.x;
    size_t n = blockIdx.x;
    const float* Xn = X + n * D * D;
    for (int e = tid; e < D * D; e += NT) {
        int i = e / D, j = e - i * D;
        sX[i * LD + j] = Xn[e];
        sP[i * LD + j] = P[e];
    }
    __syncthreads();
    for (int e = tid; e < D * D; e += NT) {
        int i = e / D, j = e - i * D;
        float acc = 0.f;
#pragma unroll 4
        for (int k = 0; k < D; k++) acc += sP[i * LD + k] * sX[k * LD + j];
        sT[i * LD + j] = acc;
    }
    __syncthreads();
    for (int e = tid; e < D * D; e += NT) {
        int i = e / D, j = e - i * D;
        float acc = 0.f;
#pragma unroll 4
        for (int k = 0; k < D; k++) acc += sT[i * LD + k] * sP[j * LD + k];
        sX[i * LD + j] = acc;
    }
    __syncthreads();
    float* Yn = Y + n * D * D;
    for (int e = tid; e < D * D; e += NT) {
        int i = e / D, j = e - i * D;
        Yn[e] = 0.5f * (sX[i * LD + j] + sX[j * LD + i]);
    }
}

// ---------------------------------------------------------------------------
// Batch-mean reduction (deterministic two stage).
// ---------------------------------------------------------------------------
template <int D>
__global__ void __launch_bounds__(NT)
red1_kernel(const float* __restrict__ src, float* __restrict__ part) {
    int e = blockIdx.x * NT + threadIdx.x;
    int g = blockIdx.y;
    if (e >= D * D) return;
    float s = 0.f;
    const float* p = src + (size_t)g * SPG * D * D + e;
    for (int i = 0; i < SPG; i++) s += p[(size_t)i * D * D];
    part[g * D * D + e] = s;
}

template <int D>
__global__ void __launch_bounds__(NT)
red2_kernel(const float* __restrict__ part, float* __restrict__ dst) {
    __shared__ float Msh[D * D];
    int tid = threadIdx.x;
    for (int e = tid; e < D * D; e += NT) {
        float s = 0.f;
        for (int g = 0; g < NGRP; g++) s += part[g * D * D + e];
        Msh[e] = s * (1.f / (float)NSAMP);
    }
    __syncthreads();
    for (int e = tid; e < D * D; e += NT) {
        int i = e / D, j = e - i * D;
        dst[e] = 0.5f * (Msh[e] + Msh[j * D + i]);
    }
}

// ---------------------------------------------------------------------------
// Single-matrix eig kernels (1 block each, two-sided engine).
// ---------------------------------------------------------------------------
#define EIG_DECL(D)                                              \
    constexpr int LD = (D) + 1;                                  \
    __shared__ float U0[(D) * LD]; __shared__ float U2[(D) * LD]; \
    __shared__ float sc[(D) / 2]; __shared__ float ssn[(D) / 2];  \
    __shared__ int sp[(D) / 2]; __shared__ int sq[(D) / 2];       \
    __shared__ float sred[9]; __shared__ float sf[(D)];           \
    int tid = threadIdx.x;

// Ws = sqrtm(sym(Gw))
template <int D>
__global__ void __launch_bounds__(NT)
ws_kernel(const float* __restrict__ Gw, float* __restrict__ Ws) {
    EIG_DECL(D)
    for (int e = tid; e < D * D; e += NT) {
        int i = e / D, j = e - i * D;
        U0[i * LD + j] = 0.5f * (Gw[e] + Gw[j * D + i]);
    }
    __syncthreads();
    jacobi<D>(U0, U2, sc, ssn, sp, sq, sred, tid);
    for (int k = tid; k < D; k += NT) sf[k] = sqrtf(fmaxf(U0[k * LD + k], 0.f));
    __syncthreads();
    for (int e = tid; e < D * D; e += NT) {
        int i = e / D, j = e - i * D;
        float acc = 0.f;
#pragma unroll 4
        for (int k = 0; k < D; k++) acc += U2[i * LD + k] * sf[k] * U2[j * LD + k];
        Ws[e] = acc;
    }
}

// M0s = sqrtm(M0), M0is = isqrtm(M0)
template <int D>
__global__ void __launch_bounds__(NT)
eig_m0_kernel(const float* __restrict__ M0,
              float* __restrict__ M0s, float* __restrict__ M0is) {
    EIG_DECL(D)
    for (int e = tid; e < D * D; e += NT) {
        int i = e / D, j = e - i * D;
        U0[i * LD + j] = M0[e];
    }
    __syncthreads();
    jacobi<D>(U0, U2, sc, ssn, sp, sq, sred, tid);
    for (int k = tid; k < D; k += NT) sf[k] = sqrtf(fmaxf(U0[k * LD + k], 1e-30f));
    __syncthreads();
    for (int e = tid; e < D * D; e += NT) {
        int i = e / D, j = e - i * D;
        float acc = 0.f;
#pragma unroll 4
        for (int k = 0; k < D; k++) acc += U2[i * LD + k] * sf[k] * U2[j * LD + k];
        M0s[e] = acc;
    }
    __syncthreads();
    for (int k = tid; k < D; k += NT) sf[k] = 1.f / sf[k];
    __syncthreads();
    for (int e = tid; e < D * D; e += NT) {
        int i = e / D, j = e - i * D;
        float acc = 0.f;
#pragma unroll 4
        for (int k = 0; k < D; k++) acc += U2[i * LD + k] * sf[k] * U2[j * LD + k];
        M0is[e] = acc;
    }
}

// G = sym(M0s expm(L) M0s)  -- L indefinite: two-sided engine required.
template <int D>
__global__ void __launch_bounds__(NT)
formG_kernel(const float* __restrict__ L,
             const float* __restrict__ M0s, float* __restrict__ G) {
    EIG_DECL(D)
    __shared__ float U1[D * LD];
    for (int e = tid; e < D * D; e += NT) {
        int i = e / D, j = e - i * D;
        U0[i * LD + j] = L[e];
        U1[i * LD + j] = M0s[e];
    }
    __syncthreads();
    jacobi<D>(U0, U2, sc, ssn, sp, sq, sred, tid);
    for (int k = tid; k < D; k += NT) sf[k] = expf(U0[k * LD + k]);
    __syncthreads();
    {
        float tmp[(D * D + NT - 1) / NT];
        int c = 0;
        for (int e = tid; e < D * D; e += NT) {
            int i = e / D, j = e - i * D;
            float acc = 0.f;
#pragma unroll 4
            for (int k = 0; k < D; k++) acc += U2[i * LD + k] * sf[k] * U2[j * LD + k];
            tmp[c++] = acc;
        }
        __syncthreads();
        c = 0;
        for (int e = tid; e < D * D; e += NT) {
            int i = e / D, j = e - i * D;
            U0[i * LD + j] = tmp[c++];
        }
        __syncthreads();
    }
    for (int e = tid; e < D * D; e += NT) {
        int i = e / D, j = e - i * D;
        float acc = 0.f;
#pragma unroll 4
        for (int k = 0; k < D; k++) acc += U1[i * LD + k] * U0[k * LD + j];
        U2[i * LD + j] = acc;
    }
    __syncthreads();
    {
        float tmp[(D * D + NT - 1) / NT];
        int c = 0;
        for (int e = tid; e < D * D; e += NT) {
            int i = e / D, j = e - i * D;
            float acc = 0.f;
#pragma unroll 4
            for (int k = 0; k < D; k++) acc += U2[i * LD + k] * U1[k * LD + j];
            tmp[c++] = acc;
        }
        __syncthreads();
        c = 0;
        for (int e = tid; e < D * D; e += NT) {
            int i = e / D, j = e - i * D;
            U0[i * LD + j] = tmp[c++];
        }
        __syncthreads();
        for (int e = tid; e < D * D; e += NT) {
            int i = e / D, j = e - i * D;
            G[e] = 0.5f * (U0[i * LD + j] + U0[j * LD + i]);
        }
    }
}

// P = Ws @ isqrtm(G)
template <int D>
__global__ void __launch_bounds__(NT)
eig_p_kernel(const float* __restrict__ G,
             const float* __restrict__ Ws, float* __restrict__ P) {
    EIG_DECL(D)
    __shared__ float U1[D * LD];
    for (int e = tid; e < D * D; e += NT) {
        int i = e / D, j = e - i * D;
        U0[i * LD + j] = G[e];
        U1[i * LD + j] = Ws[e];
    }
    __syncthreads();
    jacobi<D>(U0, U2, sc, ssn, sp, sq, sred, tid);
    for (int k = tid; k < D; k += NT)
        sf[k] = 1.f / sqrtf(fmaxf(U0[k * LD + k], 1e-30f));
    __syncthreads();
    {
        float tmp[(D * D + NT - 1) / NT];
        int c = 0;
        for (int e = tid; e < D * D; e += NT) {
            int i = e / D, j = e - i * D;
            float acc = 0.f;
#pragma unroll 4
            for (int k = 0; k < D; k++) acc += U2[i * LD + k] * sf[k] * U2[j * LD + k];
            tmp[c++] = acc;
        }
        __syncthreads();
        c = 0;
        for (int e = tid; e < D * D; e += NT) {
            int i = e / D, j = e - i * D;
            U0[i * LD + j] = tmp[c++];
        }
        __syncthreads();
    }
    for (int e = tid; e < D * D; e += NT) {
        int i = e / D, j = e - i * D;
        float acc = 0.f;
#pragma unroll 4
        for (int k = 0; k < D; k++) acc += U1[i * LD + k] * U0[k * LD + j];
        P[e] = acc;
    }
}

// ---------------------------------------------------------------------------
extern "C" void kernel_launch(void* const* d_in, const int* in_sizes, int n_in,
                              void* d_out, int out_size) {
    (void)in_sizes; (void)n_in; (void)out_size;
    const float* x  = (const float*)d_in[0];
    const float* W1 = (const float*)d_in[1];
    const float* W2 = (const float*)d_in[2];
    const float* W3 = (const float*)d_in[3];
    const float* G1 = (const float*)d_in[4];
    const float* G2 = (const float*)d_in[5];
    const float* G3 = (const float*)d_in[6];
    const float* Wl = (const float*)d_in[7];
    const float* bl = (const float*)d_in[8];
    float* out  = (float*)d_out;
    float* outY = out;
    float* outF = out + (size_t)NSAMP * 2;

    float *bufA, *bufB, *part, *accM, *accL, *m0s, *m0is, *gG, *gP, *ws1, *ws2, *ws3;
    cudaGetSymbolAddress((void**)&bufA, g_bufA);
    cudaGetSymbolAddress((void**)&bufB, g_bufB);
    cudaGetSymbolAddress((void**)&part, g_part);
    cudaGetSymbolAddress((void**)&accM, g_accM);
    cudaGetSymbolAddress((void**)&accL, g_accL);
    cudaGetSymbolAddress((void**)&m0s,  g_M0s);
    cudaGetSymbolAddress((void**)&m0is, g_M0is);
    cudaGetSymbolAddress((void**)&gG,   g_G);
    cudaGetSymbolAddress((void**)&gP,   g_P);
    cudaGetSymbolAddress((void**)&ws1,  g_Ws1);
    cudaGetSymbolAddress((void**)&ws2,  g_Ws2);
    cudaGetSymbolAddress((void**)&ws3,  g_Ws3);

    // sqrtm of the learned SPD biases (independent)
    ws_kernel<58><<<1, NT>>>(G1, ws1);
    ws_kernel<54><<<1, NT>>>(G2, ws2);
    ws_kernel<50><<<1, NT>>>(G3, ws3);

    // ---------------- Layer 1 (62 -> 58): curr in bufA ----------------
    {
        const int D = 58;
        const int EB = (D * D + NT - 1) / NT;
        bimap_kernel<62, 58><<<NSAMP, NT>>>(x, W1, bufA);
        red1_kernel<D><<<dim3(EB, NGRP), NT>>>(bufA, part);
        red2_kernel<D><<<1, NT>>>(part, accM);
        eig_m0_kernel<D><<<1, NT>>>(accM, m0s, m0is);
        congr_kernel<D><<<NSAMP, NT>>>(bufA, m0is, bufB);   // B = sym(M0is X M0is)
        eig_log_kernel<D><<<NSAMP, NT>>>(bufB);             // B <- logm(B)
        red1_kernel<D><<<dim3(EB, NGRP), NT>>>(bufB, part);
        red2_kernel<D><<<1, NT>>>(part, accL);
        formG_kernel<D><<<1, NT>>>(accL, m0s, gG);
        eig_p_kernel<D><<<1, NT>>>(gG, ws1, gP);
        congr_kernel<D><<<NSAMP, NT>>>(bufA, gP, bufB);     // B = sym(P X P^T)
        eig_clamp_kernel<D><<<NSAMP, NT>>>(bufB);           // B <- ReEig(B)
    }
    // ---------------- Layer 2 (58 -> 54): curr in bufB ----------------
    {
        const int D = 54;
        const int EB = (D * D + NT - 1) / NT;
        bimap_kernel<58, 54><<<NSAMP, NT>>>(bufB, W2, bufA);
        red1_kernel<D><<<dim3(EB, NGRP), NT>>>(bufA, part);
        red2_kernel<D><<<1, NT>>>(part, accM);
        eig_m0_kernel<D><<<1, NT>>>(accM, m0s, m0is);
        congr_kernel<D><<<NSAMP, NT>>>(bufA, m0is, bufB);
        eig_log_kernel<D><<<NSAMP, NT>>>(bufB);
        red1_kernel<D><<<dim3(EB, NGRP), NT>>>(bufB, part);
        red2_kernel<D><<<1, NT>>>(part, accL);
        formG_kernel<D><<<1, NT>>>(accL, m0s, gG);
        eig_p_kernel<D><<<1, NT>>>(gG, ws2, gP);
        congr_kernel<D><<<NSAMP, NT>>>(bufA, gP, bufB);
        eig_clamp_kernel<D><<<NSAMP, NT>>>(bufB);
    }
    // ---------------- Layer 3 (54 -> 50): curr in bufB ----------------
    {
        const int D = 50;
        const int EB = (D * D + NT - 1) / NT;
        bimap_kernel<54, 50><<<NSAMP, NT>>>(bufB, W3, bufA);
        red1_kernel<D><<<dim3(EB, NGRP), NT>>>(bufA, part);
        red2_kernel<D><<<1, NT>>>(part, accM);
        eig_m0_kernel<D><<<1, NT>>>(accM, m0s, m0is);
        congr_kernel<D><<<NSAMP, NT>>>(bufA, m0is, bufB);
        eig_log_kernel<D><<<NSAMP, NT>>>(bufB);
        red1_kernel<D><<<dim3(EB, NGRP), NT>>>(bufB, part);
        red2_kernel<D><<<1, NT>>>(part, accL);
        formG_kernel<D><<<1, NT>>>(accL, m0s, gG);
        eig_p_kernel<D><<<1, NT>>>(gG, ws3, gP);
        congr_kernel<D><<<NSAMP, NT>>>(bufA, gP, outF);     // feat -> d_out
        eig_y_kernel<D><<<NSAMP, NT>>>(outF, Wl, bl, outY); // y -> d_out
    }
}